// round 2
// baseline (speedup 1.0000x reference)
#include <cuda_runtime.h>
#include <math.h>

// One thread = 4 consecutive output pixels along W, all 3 channels.
// Affine matrix computed per-thread in fp32 (closed form:
// overall = fw^-1 * diag(1/l1,1/l2,1) * fw, translation terms are exactly 0).
__global__ __launch_bounds__(128)
void warp_kernel(const float* __restrict__ x, float* __restrict__ out,
                 const float* __restrict__ thetas,
                 const float* __restrict__ l1s,
                 const float* __restrict__ l2s,
                 int H, int W) {
    const int b = blockIdx.z;
    const int h = blockIdx.y;
    const int w0 = (blockIdx.x * blockDim.x + threadIdx.x) * 4;
    if (w0 >= W) return;

    // --- per-thread matrix (broadcast loads, cached) ---
    float th = thetas[b];
    float c, s;
    __sincosf(th, &s, &c);          // fast-math sin/cos
    float i1 = 1.0f / l1s[b];
    float i2 = 1.0f / l2s[b];
    float A00 = c * c * i1 + s * s * i2;
    float A01 = c * s * (i1 - i2);
    float A10 = A01;
    float A11 = s * s * i1 + c * c * i2;

    // --- grid coords for first pixel + per-pixel increments ---
    float xn = ((float)w0 + 0.5f) * (2.0f / (float)W) - 1.0f;
    float yn = ((float)h  + 0.5f) * (2.0f / (float)H) - 1.0f;
    float gx0 = (A00 * xn + A01 * yn + 1.0f) * ((float)W * 0.5f) - 0.5f;
    float gy0 = (A10 * xn + A11 * yn + 1.0f) * ((float)H * 0.5f) - 0.5f;
    float dgx = A00;                          // d gx / d w
    float dgy = A10 * (float)H / (float)W;    // d gy / d w

    const int HW = H * W;
    const float fW = (float)W, fH = (float)H;

    float gx[4], gy[4];
    bool inb[4];
    bool anyin = false;
    #pragma unroll
    for (int i = 0; i < 4; i++) {
        gx[i] = fmaf((float)i, dgx, gx0);
        gy[i] = fmaf((float)i, dgy, gy0);
        inb[i] = (gx[i] > -1.0f) && (gx[i] < fW) && (gy[i] > -1.0f) && (gy[i] < fH);
        anyin |= inb[i];
    }

    float* op = out + (long long)(b * 3) * HW + h * W + w0;

    if (!anyin) {
        const float4 z = make_float4(0.f, 0.f, 0.f, 0.f);
        __stcs((float4*)(op), z);
        __stcs((float4*)(op + HW), z);
        __stcs((float4*)(op + 2 * HW), z);
        return;
    }

    float4 r0 = make_float4(0.f, 0.f, 0.f, 0.f);
    float4 r1 = r0, r2 = r0;
    float* r0p = &r0.x; float* r1p = &r1.x; float* r2p = &r2.x;

    const float* base = x + (long long)(b * 3) * HW;

    #pragma unroll
    for (int i = 0; i < 4; i++) {
        if (!inb[i]) continue;
        float x0f = floorf(gx[i]), y0f = floorf(gy[i]);
        int x0 = (int)x0f, y0 = (int)y0f;
        int x1 = x0 + 1, y1 = y0 + 1;
        float wx1 = gx[i] - x0f, wx0 = 1.0f - wx1;
        float wy1 = gy[i] - y0f, wy0 = 1.0f - wy1;

        float fx0 = (x0 >= 0) ? wx0 : 0.0f;        // x0 < W guaranteed (gx < W)
        float fx1 = (x1 < W) ? wx1 : 0.0f;         // x1 >= 0 guaranteed
        float fy0 = (y0 >= 0) ? wy0 : 0.0f;
        float fy1 = (y1 < H) ? wy1 : 0.0f;

        int xc0 = max(x0, 0);
        int xc1 = min(x1, W - 1);
        int yc0 = max(y0, 0);
        int yc1 = min(y1, H - 1);

        int o00 = yc0 * W + xc0;
        int o01 = yc0 * W + xc1;
        int o10 = yc1 * W + xc0;
        int o11 = yc1 * W + xc1;

        float w00 = fy0 * fx0, w01 = fy0 * fx1;
        float w10 = fy1 * fx0, w11 = fy1 * fx1;

        const float* p0 = base;
        const float* p1 = base + HW;
        const float* p2 = base + 2 * HW;
        r0p[i] = w00 * __ldg(p0 + o00) + w01 * __ldg(p0 + o01) +
                 w10 * __ldg(p0 + o10) + w11 * __ldg(p0 + o11);
        r1p[i] = w00 * __ldg(p1 + o00) + w01 * __ldg(p1 + o01) +
                 w10 * __ldg(p1 + o10) + w11 * __ldg(p1 + o11);
        r2p[i] = w00 * __ldg(p2 + o00) + w01 * __ldg(p2 + o01) +
                 w10 * __ldg(p2 + o10) + w11 * __ldg(p2 + o11);
    }

    __stcs((float4*)(op), r0);
    __stcs((float4*)(op + HW), r1);
    __stcs((float4*)(op + 2 * HW), r2);
}

extern "C" void kernel_launch(void* const* d_in, const int* in_sizes, int n_in,
                              void* d_out, int out_size) {
    const float* x      = (const float*)d_in[0];
    const float* thetas = (const float*)d_in[1];
    const float* l1s    = (const float*)d_in[2];
    const float* l2s    = (const float*)d_in[3];
    float* out = (float*)d_out;

    int B = in_sizes[1];
    long long hw = (long long)in_sizes[0] / ((long long)B * 3);
    int W = (int)(sqrt((double)hw) + 0.5);
    int H = (int)(hw / W);

    dim3 block(128, 1, 1);
    dim3 grid((W + 4 * 128 - 1) / (4 * 128), H, B);
    warp_kernel<<<grid, block>>>(x, out, thetas, l1s, l2s, H, W);
}

// round 3
// speedup vs baseline: 1.1115x; 1.1115x over previous
#include <cuda_runtime.h>
#include <math.h>

// One thread = 1 output pixel, all 3 channels. 2D tile 32x8 for gather locality.
// Affine matrix closed form: overall = fw^-1 * diag(1/l1,1/l2,1) * fw;
// translation terms are exactly zero.
__global__ __launch_bounds__(256)
void warp_kernel(const float* __restrict__ x, float* __restrict__ out,
                 const float* __restrict__ thetas,
                 const float* __restrict__ l1s,
                 const float* __restrict__ l2s,
                 int H, int W) {
    const int b = blockIdx.z;
    const int w = blockIdx.x * 32 + threadIdx.x;
    const int h = blockIdx.y * 8 + threadIdx.y;
    if (w >= W || h >= H) return;

    // --- per-thread matrix (broadcast loads, L1-cached) ---
    float th = thetas[b];
    float c, s;
    __sincosf(th, &s, &c);
    float i1 = 1.0f / l1s[b];
    float i2 = 1.0f / l2s[b];
    float A00 = c * c * i1 + s * s * i2;
    float A01 = c * s * (i1 - i2);
    float A11 = s * s * i1 + c * c * i2;

    float xn = ((float)w + 0.5f) * (2.0f / (float)W) - 1.0f;
    float yn = ((float)h + 0.5f) * (2.0f / (float)H) - 1.0f;
    float gx = (A00 * xn + A01 * yn + 1.0f) * ((float)W * 0.5f) - 0.5f;
    float gy = (A01 * xn + A11 * yn + 1.0f) * ((float)H * 0.5f) - 0.5f;

    const int HW = H * W;
    float* op = out + (long long)(b * 3) * HW + h * W + w;

    if (!(gx > -1.0f) || gx >= (float)W || !(gy > -1.0f) || gy >= (float)H) {
        __stcs(op, 0.0f);
        __stcs(op + HW, 0.0f);
        __stcs(op + 2 * HW, 0.0f);
        return;
    }

    float x0f = floorf(gx), y0f = floorf(gy);
    int x0 = (int)x0f, y0 = (int)y0f;
    int x1 = x0 + 1, y1 = y0 + 1;
    float wx1 = gx - x0f, wx0 = 1.0f - wx1;
    float wy1 = gy - y0f, wy0 = 1.0f - wy1;

    // in-bounds guarantees: x0 < W, x1 >= 0, y0 < H, y1 >= 0
    float fx0 = (x0 >= 0) ? wx0 : 0.0f;
    float fx1 = (x1 < W) ? wx1 : 0.0f;
    float fy0 = (y0 >= 0) ? wy0 : 0.0f;
    float fy1 = (y1 < H) ? wy1 : 0.0f;

    int xc0 = max(x0, 0);
    int xc1 = min(x1, W - 1);
    int yc0 = max(y0, 0);
    int yc1 = min(y1, H - 1);

    int o00 = yc0 * W + xc0;
    int o01 = yc0 * W + xc1;
    int o10 = yc1 * W + xc0;
    int o11 = yc1 * W + xc1;

    float w00 = fy0 * fx0, w01 = fy0 * fx1;
    float w10 = fy1 * fx0, w11 = fy1 * fx1;

    const float* p0 = x + (long long)(b * 3) * HW;
    const float* p1 = p0 + HW;
    const float* p2 = p1 + HW;

    // 12 independent gathers -> max MLP
    float v000 = __ldg(p0 + o00), v001 = __ldg(p0 + o01);
    float v010 = __ldg(p0 + o10), v011 = __ldg(p0 + o11);
    float v100 = __ldg(p1 + o00), v101 = __ldg(p1 + o01);
    float v110 = __ldg(p1 + o10), v111 = __ldg(p1 + o11);
    float v200 = __ldg(p2 + o00), v201 = __ldg(p2 + o01);
    float v210 = __ldg(p2 + o10), v211 = __ldg(p2 + o11);

    __stcs(op,          w00 * v000 + w01 * v001 + w10 * v010 + w11 * v011);
    __stcs(op + HW,     w00 * v100 + w01 * v101 + w10 * v110 + w11 * v111);
    __stcs(op + 2 * HW, w00 * v200 + w01 * v201 + w10 * v210 + w11 * v211);
}

extern "C" void kernel_launch(void* const* d_in, const int* in_sizes, int n_in,
                              void* d_out, int out_size) {
    const float* x      = (const float*)d_in[0];
    const float* thetas = (const float*)d_in[1];
    const float* l1s    = (const float*)d_in[2];
    const float* l2s    = (const float*)d_in[3];
    float* out = (float*)d_out;

    int B = in_sizes[1];
    long long hw = (long long)in_sizes[0] / ((long long)B * 3);
    int W = (int)(sqrt((double)hw) + 0.5);
    int H = (int)(hw / W);

    dim3 block(32, 8, 1);
    dim3 grid((W + 31) / 32, (H + 7) / 8, B);
    warp_kernel<<<grid, block>>>(x, out, thetas, l1s, l2s, H, W);
}

// round 4
// speedup vs baseline: 1.1992x; 1.0789x over previous
#include <cuda_runtime.h>
#include <math.h>

// One thread = 1 output pixel, all 3 channels. 32x8 tile.
// Matrix computed once per block (thread 0) and broadcast via smem.
// Closed form: overall = fw^-1 * diag(1/l1,1/l2,1) * fw; translation = 0.
__global__ __launch_bounds__(256)
void warp_kernel(const float* __restrict__ x, float* __restrict__ out,
                 const float* __restrict__ thetas,
                 const float* __restrict__ l1s,
                 const float* __restrict__ l2s,
                 int H, int W) {
    __shared__ float sA[3];   // A00, A01, A11

    const int b = blockIdx.z;
    if (threadIdx.x == 0 && threadIdx.y == 0) {
        float th = thetas[b];
        float c, s;
        __sincosf(th, &s, &c);
        float i1 = 1.0f / l1s[b];
        float i2 = 1.0f / l2s[b];
        sA[0] = c * c * i1 + s * s * i2;
        sA[1] = c * s * (i1 - i2);
        sA[2] = s * s * i1 + c * c * i2;
    }
    __syncthreads();

    const int w = blockIdx.x * 32 + threadIdx.x;
    const int h = blockIdx.y * 8 + threadIdx.y;

    const float A00 = sA[0], A01 = sA[1], A11 = sA[2];

    float xn = ((float)w + 0.5f) * (2.0f / (float)W) - 1.0f;
    float yn = ((float)h + 0.5f) * (2.0f / (float)H) - 1.0f;
    float gx = (A00 * xn + A01 * yn + 1.0f) * ((float)W * 0.5f) - 0.5f;
    float gy = (A01 * xn + A11 * yn + 1.0f) * ((float)H * 0.5f) - 0.5f;

    const int HW = H * W;
    float* op = out + (long long)(b * 3) * HW + h * W + w;

    if (!(gx > -1.0f) || gx >= (float)W || !(gy > -1.0f) || gy >= (float)H) {
        __stcs(op, 0.0f);
        __stcs(op + HW, 0.0f);
        __stcs(op + 2 * HW, 0.0f);
        return;
    }

    float x0f = floorf(gx), y0f = floorf(gy);
    int x0 = (int)x0f, y0 = (int)y0f;
    int x1 = x0 + 1, y1 = y0 + 1;
    float wx1 = gx - x0f, wx0 = 1.0f - wx1;
    float wy1 = gy - y0f, wy0 = 1.0f - wy1;

    // in-bounds guarantees from the early-out: x0 < W, x1 >= 0, y0 < H, y1 >= 0
    float fx0 = (x0 >= 0) ? wx0 : 0.0f;
    float fx1 = (x1 < W) ? wx1 : 0.0f;
    float fy0 = (y0 >= 0) ? wy0 : 0.0f;
    float fy1 = (y1 < H) ? wy1 : 0.0f;

    int xc0 = max(x0, 0);
    int xc1 = min(x1, W - 1);
    int yc0 = max(y0, 0);
    int yc1 = min(y1, H - 1);

    int o00 = yc0 * W + xc0;
    int o01 = yc0 * W + xc1;
    int o10 = yc1 * W + xc0;
    int o11 = yc1 * W + xc1;

    float w00 = fy0 * fx0, w01 = fy0 * fx1;
    float w10 = fy1 * fx0, w11 = fy1 * fx1;

    const float* p0 = x + (long long)(b * 3) * HW;
    const float* p1 = p0 + HW;
    const float* p2 = p1 + HW;

    // 12 independent gathers -> max MLP
    float v000 = __ldg(p0 + o00), v001 = __ldg(p0 + o01);
    float v010 = __ldg(p0 + o10), v011 = __ldg(p0 + o11);
    float v100 = __ldg(p1 + o00), v101 = __ldg(p1 + o01);
    float v110 = __ldg(p1 + o10), v111 = __ldg(p1 + o11);
    float v200 = __ldg(p2 + o00), v201 = __ldg(p2 + o01);
    float v210 = __ldg(p2 + o10), v211 = __ldg(p2 + o11);

    __stcs(op,          w00 * v000 + w01 * v001 + w10 * v010 + w11 * v011);
    __stcs(op + HW,     w00 * v100 + w01 * v101 + w10 * v110 + w11 * v111);
    __stcs(op + 2 * HW, w00 * v200 + w01 * v201 + w10 * v210 + w11 * v211);
}

extern "C" void kernel_launch(void* const* d_in, const int* in_sizes, int n_in,
                              void* d_out, int out_size) {
    const float* x      = (const float*)d_in[0];
    const float* thetas = (const float*)d_in[1];
    const float* l1s    = (const float*)d_in[2];
    const float* l2s    = (const float*)d_in[3];
    float* out = (float*)d_out;

    int B = in_sizes[1];
    long long hw = (long long)in_sizes[0] / ((long long)B * 3);
    int W = (int)(sqrt((double)hw) + 0.5);
    int H = (int)(hw / W);

    dim3 block(32, 8, 1);
    dim3 grid((W + 31) / 32, (H + 7) / 8, B);
    warp_kernel<<<grid, block>>>(x, out, thetas, l1s, l2s, H, W);
}